// round 9
// baseline (speedup 1.0000x reference)
#include <cuda_runtime.h>
#include <cstdint>

// Problem constants
#define BN   4
#define CN   128
#define HN   128
#define WN   128
#define COUT 128
#define DGN  8
#define CG   16
#define KK   9
#define HO   128
#define WO   128
#define NS   72         // (dg,k) positions
#define KT   (NS * 2)   // k8 slices (K = 1152)

// Scratch
__device__ __align__(16) float g_xt[BN * DGN * HN * WN * CG];    // x -> (B,DG,H,W,Cg)
__device__ __align__(16) uint32_t g_wa[KT * 8 * 32 * 4];         // A-fragment-ordered tf32 weights

__device__ __forceinline__ uint32_t f2tf32(float v) {
    uint32_t r;
    asm("cvt.rna.tf32.f32 %0, %1;" : "=r"(r) : "f"(v));
    return r;
}
__device__ __forceinline__ void mma_tf32(float* d, const uint32_t* a, const uint32_t* b) {
    asm volatile(
        "mma.sync.aligned.m16n8k8.row.col.f32.tf32.tf32.f32 "
        "{%0,%1,%2,%3}, {%4,%5,%6,%7}, {%8,%9}, {%0,%1,%2,%3};"
        : "+f"(d[0]), "+f"(d[1]), "+f"(d[2]), "+f"(d[3])
        : "r"(a[0]), "r"(a[1]), "r"(a[2]), "r"(a[3]), "r"(b[0]), "r"(b[1]));
}

// ---------------------------------------------------------------------------
// Kernel 1: transpose x (B,C,H,W) -> (B, DG, H, W, Cg)
// ---------------------------------------------------------------------------
__global__ void transpose_x_kernel(const float* __restrict__ x) {
    int blk = blockIdx.x;
    int y   = blk & (HN - 1);
    int bdg = blk >> 7;
    int b   = bdg >> 3;
    int dg  = bdg & 7;
    int t   = threadIdx.x;

    __shared__ float sm[CG][WN + 1];
    #pragma unroll
    for (int c = 0; c < CG; c++)
        sm[c][t] = x[((b * CN + dg * CG + c) * HN + y) * WN + t];
    __syncthreads();

    float* outp = g_xt + ((bdg * HN + y) * WN + t) * CG;
    #pragma unroll
    for (int i = 0; i < 4; i++) {
        float4 v = make_float4(sm[i * 4 + 0][t], sm[i * 4 + 1][t],
                               sm[i * 4 + 2][t], sm[i * 4 + 3][t]);
        *(float4*)(outp + i * 4) = v;
    }
}

// ---------------------------------------------------------------------------
// Kernel 2: weight -> A-fragment-ordered tf32 (verified layout)
// ---------------------------------------------------------------------------
__global__ void prep_w_kernel(const float* __restrict__ w) {
    int i = blockIdx.x * 256 + threadIdx.x;
    if (i >= KT * 8 * 32 * 4) return;
    int j    = i & 3;
    int lane = (i >> 2) & 31;
    int mt   = (i >> 7) & 7;
    int kt   = i >> 10;
    int g    = lane >> 2;
    int tid  = lane & 3;
    int co   = mt * 16 + g + ((j & 1) ? 8 : 0);
    int col  = tid + ((j >= 2) ? 4 : 0);
    int s    = kt >> 1;
    int c    = (kt & 1) * 8 + col;
    int dg   = s / KK;
    int k    = s - dg * KK;
    g_wa[i] = f2tf32(w[(co * CN + dg * CG + c) * KK + k]);
}

// ---------------------------------------------------------------------------
// Corner prefetch state: 4 channels (one float4 per corner) + folded weights
// ---------------------------------------------------------------------------
struct C4 { float4 c[4]; float w[4]; };

__device__ __forceinline__ void issue_c4(int s, int b, int ho, int p, int q,
                                         float dy, float dx, float m, C4& C) {
    int dg = s / KK, k = s - dg * KK;
    int ky = k / 3, kx = k - ky * 3;
    float sy = dy + (float)(ho - 1 + ky);   // STRIDE=1, PAD=1, DIL=1
    float sx = dx + (float)(p - 1 + kx);
    float y0f = floorf(sy), x0f = floorf(sx);
    float ly = sy - y0f, lx = sx - x0f;
    int y0 = (int)y0f, x0 = (int)x0f;
    float ww[4] = {(1.0f - ly) * (1.0f - lx) * m, (1.0f - ly) * lx * m,
                   ly * (1.0f - lx) * m,          ly * lx * m};
    const float* xb = g_xt + (b * DGN + dg) * (HN * WN * CG) + q * 4;
    #pragma unroll
    for (int i = 0; i < 4; i++) {
        int yy = y0 + (i >> 1), xx = x0 + (i & 1);
        bool v = (yy >= 0) & (yy < HN) & (xx >= 0) & (xx < WN);
        int cy = min(max(yy, 0), HN - 1), cx = min(max(xx, 0), WN - 1);
        C.c[i] = __ldg((const float4*)(xb + (cy * WN + cx) * CG));
        C.w[i] = v ? ww[i] : 0.0f;
    }
}

// ---------------------------------------------------------------------------
// Kernel 3: depth-2 pipelined sampling + tf32 mma.sync implicit GEMM.
// 512 threads / 16 warps per (b,ho) block. Warp tile 32(co) x 32(px).
// Thread t samples pixel (t>>2), channel quarter (t&3) -- coalesced gathers.
// Corners for stage s+2 issued at stage s (two C4 sets in flight); offsets
// prefetched at depth 3; A slice at depth 1; single __syncthreads per stage.
// ---------------------------------------------------------------------------
__global__ __launch_bounds__(512)
void dcn_main_kernel(const float* __restrict__ offset,
                     const float* __restrict__ mask,
                     const float* __restrict__ bias,
                     float*       __restrict__ out) {
    int blk = blockIdx.x;
    int ho  = blk & (HO - 1);
    int b   = blk >> 7;
    int t   = threadIdx.x;
    int wid = t >> 5;
    int lane = t & 31;

    // B frags: [buf][kt][ntile][lane][half] u32 -> 16KB
    __shared__ __align__(16) uint32_t bfr[2][2][16][32][2];
    // A frags: [buf][kt][mtile][lane] uint4     -> 16KB
    __shared__ __align__(16) uint4 afrag[2][2][8][32];

    int m0 = (wid >> 2) * 2;   // 2 mtiles per warp
    int n0 = (wid & 3) * 4;    // 4 ntiles per warp

    // sampler mapping: 4 threads per pixel, one pass
    int q    = t & 3;          // channel quarter
    int p    = t >> 2;         // pixel (0..127)
    int kt   = q >> 1;         // k8-slice
    int half = q & 1;          // b0 vs b1 rows

    float d[2][4][4];
    #pragma unroll
    for (int mi = 0; mi < 2; mi++)
        #pragma unroll
        for (int ni = 0; ni < 4; ni++)
            #pragma unroll
            for (int j = 0; j < 4; j++) d[mi][ni][j] = 0.0f;

    // ---- prologue: corners(0), corners(1) in flight; ofs(2) pending ----
    C4 C[2];
    uint4 aP0;
    float dyN, dxN, mN;
    {
        int ob0 = ((b * (2 * NS)) * HO + ho) * WO;
        float dy = __ldg(offset + ob0 + p);
        float dx = __ldg(offset + ob0 + HO * WO + p);
        float mm = __ldg(mask + (b * NS * HO + ho) * WO + p);
        issue_c4(0, b, ho, p, q, dy, dx, mm, C[0]);

        int ob1 = ((b * (2 * NS) + 2) * HO + ho) * WO;
        dy = __ldg(offset + ob1 + p);
        dx = __ldg(offset + ob1 + HO * WO + p);
        mm = __ldg(mask + ((b * NS + 1) * HO + ho) * WO + p);
        issue_c4(1, b, ho, p, q, dy, dx, mm, C[1]);

        int ob2 = ((b * (2 * NS) + 4) * HO + ho) * WO;
        dyN = __ldg(offset + ob2 + p);
        dxN = __ldg(offset + ob2 + HO * WO + p);
        mN  = __ldg(mask + ((b * NS + 2) * HO + ho) * WO + p);

        aP0 = __ldg((const uint4*)g_wa + t);   // A(0): 512 uint4, one per thread
    }

    for (int s = 0; s < NS; s++) {
        int buf = s & 1;

        // ---- store prefetched A(s) ----
        ((uint4*)&afrag[buf][0][0][0])[t] = aP0;

        // ---- combine corners(s) -> B frags ----
        {
            C4& Cc = C[s & 1];
            float val[4];
            #pragma unroll
            for (int c = 0; c < 4; c++) {
                const float* f0 = (const float*)&Cc.c[0];
                const float* f1 = (const float*)&Cc.c[1];
                const float* f2 = (const float*)&Cc.c[2];
                const float* f3 = (const float*)&Cc.c[3];
                val[c] = Cc.w[0] * f0[c] + Cc.w[1] * f1[c]
                       + Cc.w[2] * f2[c] + Cc.w[3] * f3[c];
            }
            int nt = p >> 3;
            int lb = (p & 7) * 4;
            #pragma unroll
            for (int c = 0; c < 4; c++)
                bfr[buf][kt][nt][lb + c][half] = f2tf32(val[c]);
        }

        // ---- issue corners(s+2) into the freed C4 slot; load ofs(s+3) ----
        if (s + 2 < NS) {
            issue_c4(s + 2, b, ho, p, q, dyN, dxN, mN, C[s & 1]);
            if (s + 3 < NS) {
                int ob = ((b * (2 * NS) + 2 * (s + 3)) * HO + ho) * WO;
                dyN = __ldg(offset + ob + p);
                dxN = __ldg(offset + ob + HO * WO + p);
                mN  = __ldg(mask + ((b * NS + s + 3) * HO + ho) * WO + p);
            }
        }

        // ---- prefetch A(s+1) ----
        if (s + 1 < NS)
            aP0 = __ldg((const uint4*)(g_wa + (s + 1) * 2048) + t);

        __syncthreads();   // frags(s) visible; other buffer free

        // ---- GEMM(s): 2 k8-slices x 2 mtiles x 4 ntiles m16n8k8 ----
        #pragma unroll
        for (int k2 = 0; k2 < 2; k2++) {
            uint4 af[2];
            #pragma unroll
            for (int mi = 0; mi < 2; mi++) af[mi] = afrag[buf][k2][m0 + mi][lane];
            uint2 bf[4];
            #pragma unroll
            for (int ni = 0; ni < 4; ni++)
                bf[ni] = *(const uint2*)&bfr[buf][k2][n0 + ni][lane][0];
            #pragma unroll
            for (int mi = 0; mi < 2; mi++)
                #pragma unroll
                for (int ni = 0; ni < 4; ni++)
                    mma_tf32(d[mi][ni], (const uint32_t*)&af[mi],
                             (const uint32_t*)&bf[ni]);
        }
    }

    // ---- epilogue ----
    int g   = lane >> 2;
    int tid = lane & 3;
    #pragma unroll
    for (int mi = 0; mi < 2; mi++) {
        int co0 = (m0 + mi) * 16 + g;
        float bv0 = __ldg(bias + co0);
        float bv1 = __ldg(bias + co0 + 8);
        #pragma unroll
        for (int ni = 0; ni < 4; ni++) {
            int px = (n0 + ni) * 8 + 2 * tid;
            float2 o0 = make_float2(d[mi][ni][0] + bv0, d[mi][ni][1] + bv0);
            float2 o1 = make_float2(d[mi][ni][2] + bv1, d[mi][ni][3] + bv1);
            *(float2*)(out + ((b * COUT + co0)     * HO + ho) * WO + px) = o0;
            *(float2*)(out + ((b * COUT + co0 + 8) * HO + ho) * WO + px) = o1;
        }
    }
}

// ---------------------------------------------------------------------------
// Launch
// ---------------------------------------------------------------------------
extern "C" void kernel_launch(void* const* d_in, const int* in_sizes, int n_in,
                              void* d_out, int out_size) {
    const float* x      = (const float*)d_in[0];
    const float* offset = (const float*)d_in[1];
    const float* mask   = (const float*)d_in[2];
    const float* weight = (const float*)d_in[3];
    const float* bias   = (const float*)d_in[4];
    float* out = (float*)d_out;

    transpose_x_kernel<<<BN * DGN * HN, 128>>>(x);
    prep_w_kernel<<<(KT * 8 * 32 * 4 + 255) / 256, 256>>>(weight);
    dcn_main_kernel<<<BN * HO, 512>>>(offset, mask, bias, out);
}

// round 10
// speedup vs baseline: 2.0377x; 2.0377x over previous
#include <cuda_runtime.h>
#include <cstdint>

// Problem constants
#define BN   4
#define CN   128
#define HN   128
#define WN   128
#define COUT 128
#define DGN  8
#define CG   16
#define KK   9
#define HO   128
#define WO   128
#define NS   72         // (dg,k) positions
#define KT   (NS * 2)   // k8 slices (K = 1152)
#define PXB  64         // pixels per block

// Scratch
__device__ __align__(16) float g_xt[BN * DGN * HN * WN * CG];    // x -> (B,DG,H,W,Cg)
__device__ __align__(16) uint32_t g_wa[KT * 8 * 32 * 4];         // A-fragment-ordered tf32 weights

__device__ __forceinline__ uint32_t f2tf32(float v) {
    uint32_t r;
    asm("cvt.rna.tf32.f32 %0, %1;" : "=r"(r) : "f"(v));
    return r;
}
__device__ __forceinline__ void mma_tf32(float* d, const uint32_t* a, const uint32_t* b) {
    asm volatile(
        "mma.sync.aligned.m16n8k8.row.col.f32.tf32.tf32.f32 "
        "{%0,%1,%2,%3}, {%4,%5,%6,%7}, {%8,%9}, {%0,%1,%2,%3};"
        : "+f"(d[0]), "+f"(d[1]), "+f"(d[2]), "+f"(d[3])
        : "r"(a[0]), "r"(a[1]), "r"(a[2]), "r"(a[3]), "r"(b[0]), "r"(b[1]));
}

// ---------------------------------------------------------------------------
// Kernel 1: transpose x (B,C,H,W) -> (B, DG, H, W, Cg)
// ---------------------------------------------------------------------------
__global__ void transpose_x_kernel(const float* __restrict__ x) {
    int blk = blockIdx.x;
    int y   = blk & (HN - 1);
    int bdg = blk >> 7;
    int b   = bdg >> 3;
    int dg  = bdg & 7;
    int t   = threadIdx.x;

    __shared__ float sm[CG][WN + 1];
    #pragma unroll
    for (int c = 0; c < CG; c++)
        sm[c][t] = x[((b * CN + dg * CG + c) * HN + y) * WN + t];
    __syncthreads();

    float* outp = g_xt + ((bdg * HN + y) * WN + t) * CG;
    #pragma unroll
    for (int i = 0; i < 4; i++) {
        float4 v = make_float4(sm[i * 4 + 0][t], sm[i * 4 + 1][t],
                               sm[i * 4 + 2][t], sm[i * 4 + 3][t]);
        *(float4*)(outp + i * 4) = v;
    }
}

// ---------------------------------------------------------------------------
// Kernel 2: weight -> A-fragment-ordered tf32 (verified layout)
// ---------------------------------------------------------------------------
__global__ void prep_w_kernel(const float* __restrict__ w) {
    int i = blockIdx.x * 256 + threadIdx.x;
    if (i >= KT * 8 * 32 * 4) return;
    int j    = i & 3;
    int lane = (i >> 2) & 31;
    int mt   = (i >> 7) & 7;
    int kt   = i >> 10;
    int g    = lane >> 2;
    int tid  = lane & 3;
    int co   = mt * 16 + g + ((j & 1) ? 8 : 0);
    int col  = tid + ((j >= 2) ? 4 : 0);
    int s    = kt >> 1;
    int c    = (kt & 1) * 8 + col;
    int dg   = s / KK;
    int k    = s - dg * KK;
    g_wa[i] = f2tf32(w[(co * CN + dg * CG + c) * KK + k]);
}

// ---------------------------------------------------------------------------
// Corner prefetch state (statically allocated per instance, NEVER indexed
// dynamically): 4 channels + folded weights
// ---------------------------------------------------------------------------
struct C4 { float4 c[4]; float w[4]; };

__device__ __forceinline__ void issue_c4(int s, int b, int ho, int p, int q,
                                         float dy, float dx, float m, C4& C) {
    int dg = s / KK, k = s - dg * KK;
    int ky = k / 3, kx = k - ky * 3;
    float sy = dy + (float)(ho - 1 + ky);   // STRIDE=1, PAD=1, DIL=1
    float sx = dx + (float)(p - 1 + kx);
    float y0f = floorf(sy), x0f = floorf(sx);
    float ly = sy - y0f, lx = sx - x0f;
    int y0 = (int)y0f, x0 = (int)x0f;
    float ww[4] = {(1.0f - ly) * (1.0f - lx) * m, (1.0f - ly) * lx * m,
                   ly * (1.0f - lx) * m,          ly * lx * m};
    const float* xb = g_xt + (b * DGN + dg) * (HN * WN * CG) + q * 4;
    #pragma unroll
    for (int i = 0; i < 4; i++) {
        int yy = y0 + (i >> 1), xx = x0 + (i & 1);
        bool v = (yy >= 0) & (yy < HN) & (xx >= 0) & (xx < WN);
        int cy = min(max(yy, 0), HN - 1), cx = min(max(xx, 0), WN - 1);
        C.c[i] = __ldg((const float4*)(xb + (cy * WN + cx) * CG));
        C.w[i] = v ? ww[i] : 0.0f;
    }
}

// ---------------------------------------------------------------------------
// Kernel 3: depth-2 pipelined sampling + tf32 mma.sync, 64-px blocks,
// 2 CTAs/SM. 256 threads / 8 warps; warp tile 32(co) x 32(px).
// Stage loop unrolled x2 so prefetch buffers (CE/CO, aPE/aPO, ofsE/ofsO)
// are statically named registers. Single __syncthreads per stage.
// ---------------------------------------------------------------------------
__global__ __launch_bounds__(256, 2)
void dcn_main_kernel(const float* __restrict__ offset,
                     const float* __restrict__ mask,
                     const float* __restrict__ bias,
                     float*       __restrict__ out) {
    int blk = blockIdx.x;                  // ((b*HO + ho)*2 + hr)
    int hr  = blk & 1;
    int ho  = (blk >> 1) & (HO - 1);
    int b   = blk >> 8;
    int t   = threadIdx.x;
    int wid = t >> 5;
    int lane = t & 31;

    // B frags: [buf][kt][ntile(8)][lane][half] u32 -> 8KB
    __shared__ __align__(16) uint32_t bfr[2][2][8][32][2];
    // A frags: [buf][kt][mtile(8)][lane] uint4     -> 16KB
    __shared__ __align__(16) uint4 afrag[2][2][8][32];

    int m0 = (wid & 3) * 2;    // 2 mtiles per warp
    int n0 = (wid >> 2) * 4;   // 4 ntiles per warp

    // sampler mapping: 4 threads per pixel
    int q    = t & 3;          // channel quarter
    int p    = t >> 2;         // local pixel (0..63)
    int pg   = hr * PXB + p;   // global pixel in row
    int kt   = q >> 1;         // k8-slice
    int half = q & 1;          // b0 vs b1 rows

    float d[2][4][4];
    #pragma unroll
    for (int mi = 0; mi < 2; mi++)
        #pragma unroll
        for (int ni = 0; ni < 4; ni++)
            #pragma unroll
            for (int j = 0; j < 4; j++) d[mi][ni][j] = 0.0f;

    // ---- prologue ----
    C4 CE, CO;                       // corners for even / odd stages
    uint4 aPE0, aPE1, aPO0, aPO1;    // A prefetch (even / odd)
    float dyE, dxE, mE, dyO, dxO, mO;
    {
        const int obase = (b * (2 * NS)) * HO * WO + ho * WO + pg;
        const int mbase = (b * NS) * HO * WO + ho * WO + pg;
        const int OHW = HO * WO;

        float dy = __ldg(offset + obase);
        float dx = __ldg(offset + obase + OHW);
        float mm = __ldg(mask + mbase);
        issue_c4(0, b, ho, pg, q, dy, dx, mm, CE);

        dy = __ldg(offset + obase + 2 * OHW);
        dx = __ldg(offset + obase + 3 * OHW);
        mm = __ldg(mask + mbase + OHW);
        issue_c4(1, b, ho, pg, q, dy, dx, mm, CO);

        dyE = __ldg(offset + obase + 4 * OHW);
        dxE = __ldg(offset + obase + 5 * OHW);
        mE  = __ldg(mask + mbase + 2 * OHW);
        dyO = __ldg(offset + obase + 6 * OHW);
        dxO = __ldg(offset + obase + 7 * OHW);
        mO  = __ldg(mask + mbase + 3 * OHW);

        aPE0 = __ldg((const uint4*)g_wa + t);
        aPE1 = __ldg((const uint4*)g_wa + t + 256);
        aPO0 = __ldg((const uint4*)(g_wa + 2048) + t);
        aPO1 = __ldg((const uint4*)(g_wa + 2048) + t + 256);
    }

    const int OHW = HO * WO;
    const int obase = (b * (2 * NS)) * OHW + ho * WO + pg;
    const int mbase = (b * NS) * OHW + ho * WO + pg;
    int nt = p >> 3;
    int lb = (p & 7) * 4;

    #pragma unroll 1
    for (int s = 0; s < NS; s += 2) {
        // ================= even stage s (buf 0, CE) =================
        {
            uint4* wdst = (uint4*)&afrag[0][0][0][0];
            wdst[t]       = aPE0;
            wdst[t + 256] = aPE1;

            float val[4];
            #pragma unroll
            for (int c = 0; c < 4; c++) {
                const float* f0 = (const float*)&CE.c[0];
                const float* f1 = (const float*)&CE.c[1];
                const float* f2 = (const float*)&CE.c[2];
                const float* f3 = (const float*)&CE.c[3];
                val[c] = CE.w[0] * f0[c] + CE.w[1] * f1[c]
                       + CE.w[2] * f2[c] + CE.w[3] * f3[c];
            }
            #pragma unroll
            for (int c = 0; c < 4; c++)
                bfr[0][kt][nt][lb + c][half] = f2tf32(val[c]);

            // issue corners(s+2) into CE; refill ofsE at depth 4
            if (s + 2 < NS) {
                issue_c4(s + 2, b, ho, pg, q, dyE, dxE, mE, CE);
                aPE0 = __ldg((const uint4*)(g_wa + (s + 2) * 2048) + t);
                aPE1 = __ldg((const uint4*)(g_wa + (s + 2) * 2048) + t + 256);
                if (s + 4 < NS) {
                    dyE = __ldg(offset + obase + (2 * (s + 4)) * OHW);
                    dxE = __ldg(offset + obase + (2 * (s + 4) + 1) * OHW);
                    mE  = __ldg(mask + mbase + (s + 4) * OHW);
                }
            }

            __syncthreads();

            #pragma unroll
            for (int k2 = 0; k2 < 2; k2++) {
                uint4 af[2];
                #pragma unroll
                for (int mi = 0; mi < 2; mi++) af[mi] = afrag[0][k2][m0 + mi][lane];
                uint2 bf[4];
                #pragma unroll
                for (int ni = 0; ni < 4; ni++)
                    bf[ni] = *(const uint2*)&bfr[0][k2][n0 + ni][lane][0];
                #pragma unroll
                for (int mi = 0; mi < 2; mi++)
                    #pragma unroll
                    for (int ni = 0; ni < 4; ni++)
                        mma_tf32(d[mi][ni], (const uint32_t*)&af[mi],
                                 (const uint32_t*)&bf[ni]);
            }
        }

        // ================= odd stage s+1 (buf 1, CO) =================
        {
            uint4* wdst = (uint4*)&afrag[1][0][0][0];
            wdst[t]       = aPO0;
            wdst[t + 256] = aPO1;

            float val[4];
            #pragma unroll
            for (int c = 0; c < 4; c++) {
                const float* f0 = (const float*)&CO.c[0];
                const float* f1 = (const float*)&CO.c[1];
                const float* f2 = (const float*)&CO.c[2];
                const float* f3 = (const float*)&CO.c[3];
                val[c] = CO.w[0] * f0[c] + CO.w[1] * f1[c]
                       + CO.w[2] * f2[c] + CO.w[3] * f3[c];
            }
            #pragma unroll
            for (int c = 0; c < 4; c++)
                bfr[1][kt][nt][lb + c][half] = f2tf32(val[c]);

            if (s + 3 < NS) {
                issue_c4(s + 3, b, ho, pg, q, dyO, dxO, mO, CO);
                aPO0 = __ldg((const uint4*)(g_wa + (s + 3) * 2048) + t);
                aPO1 = __ldg((const uint4*)(g_wa + (s + 3) * 2048) + t + 256);
                if (s + 5 < NS) {
                    dyO = __ldg(offset + obase + (2 * (s + 5)) * OHW);
                    dxO = __ldg(offset + obase + (2 * (s + 5) + 1) * OHW);
                    mO  = __ldg(mask + mbase + (s + 5) * OHW);
                }
            }

            __syncthreads();

            #pragma unroll
            for (int k2 = 0; k2 < 2; k2++) {
                uint4 af[2];
                #pragma unroll
                for (int mi = 0; mi < 2; mi++) af[mi] = afrag[1][k2][m0 + mi][lane];
                uint2 bf[4];
                #pragma unroll
                for (int ni = 0; ni < 4; ni++)
                    bf[ni] = *(const uint2*)&bfr[1][k2][n0 + ni][lane][0];
                #pragma unroll
                for (int mi = 0; mi < 2; mi++)
                    #pragma unroll
                    for (int ni = 0; ni < 4; ni++)
                        mma_tf32(d[mi][ni], (const uint32_t*)&af[mi],
                                 (const uint32_t*)&bf[ni]);
            }
        }
    }

    // ---- epilogue ----
    int g   = lane >> 2;
    int tid = lane & 3;
    #pragma unroll
    for (int mi = 0; mi < 2; mi++) {
        int co0 = (m0 + mi) * 16 + g;
        float bv0 = __ldg(bias + co0);
        float bv1 = __ldg(bias + co0 + 8);
        #pragma unroll
        for (int ni = 0; ni < 4; ni++) {
            int px = hr * PXB + (n0 + ni) * 8 + 2 * tid;
            float2 o0 = make_float2(d[mi][ni][0] + bv0, d[mi][ni][1] + bv0);
            float2 o1 = make_float2(d[mi][ni][2] + bv1, d[mi][ni][3] + bv1);
            *(float2*)(out + ((b * COUT + co0)     * HO + ho) * WO + px) = o0;
            *(float2*)(out + ((b * COUT + co0 + 8) * HO + ho) * WO + px) = o1;
        }
    }
}

// ---------------------------------------------------------------------------
// Launch
// ---------------------------------------------------------------------------
extern "C" void kernel_launch(void* const* d_in, const int* in_sizes, int n_in,
                              void* d_out, int out_size) {
    const float* x      = (const float*)d_in[0];
    const float* offset = (const float*)d_in[1];
    const float* mask   = (const float*)d_in[2];
    const float* weight = (const float*)d_in[3];
    const float* bias   = (const float*)d_in[4];
    float* out = (float*)d_out;

    transpose_x_kernel<<<BN * DGN * HN, 128>>>(x);
    prep_w_kernel<<<(KT * 8 * 32 * 4 + 255) / 256, 256>>>(weight);
    dcn_main_kernel<<<BN * HO * 2, 256>>>(offset, mask, bias, out);
}

// round 11
// speedup vs baseline: 2.1603x; 1.0602x over previous
#include <cuda_runtime.h>
#include <cstdint>

// Problem constants
#define BN   4
#define CN   128
#define HN   128
#define WN   128
#define COUT 128
#define DGN  8
#define CG   16
#define KK   9
#define HO   128
#define WO   128
#define NS   72         // (dg,k) positions
#define KT   (NS * 2)   // k8 slices (K = 1152)
#define PXB  64         // pixels per block

// Scratch
__device__ __align__(16) float g_xt[BN * DGN * HN * WN * CG];    // x -> (B,DG,H,W,Cg)
__device__ __align__(16) uint32_t g_wa[KT * 8 * 32 * 4];         // A-fragment-ordered tf32 weights

__device__ __forceinline__ uint32_t f2tf32(float v) {
    uint32_t r;
    asm("cvt.rna.tf32.f32 %0, %1;" : "=r"(r) : "f"(v));
    return r;
}
__device__ __forceinline__ void mma_tf32(float* d, const uint32_t* a, const uint32_t* b) {
    asm volatile(
        "mma.sync.aligned.m16n8k8.row.col.f32.tf32.tf32.f32 "
        "{%0,%1,%2,%3}, {%4,%5,%6,%7}, {%8,%9}, {%0,%1,%2,%3};"
        : "+f"(d[0]), "+f"(d[1]), "+f"(d[2]), "+f"(d[3])
        : "r"(a[0]), "r"(a[1]), "r"(a[2]), "r"(a[3]), "r"(b[0]), "r"(b[1]));
}

// ---------------------------------------------------------------------------
// Kernel 1: transpose x (B,C,H,W) -> (B, DG, H, W, Cg)
// ---------------------------------------------------------------------------
__global__ void transpose_x_kernel(const float* __restrict__ x) {
    int blk = blockIdx.x;
    int y   = blk & (HN - 1);
    int bdg = blk >> 7;
    int b   = bdg >> 3;
    int dg  = bdg & 7;
    int t   = threadIdx.x;

    __shared__ float sm[CG][WN + 1];
    #pragma unroll
    for (int c = 0; c < CG; c++)
        sm[c][t] = x[((b * CN + dg * CG + c) * HN + y) * WN + t];
    __syncthreads();

    float* outp = g_xt + ((bdg * HN + y) * WN + t) * CG;
    #pragma unroll
    for (int i = 0; i < 4; i++) {
        float4 v = make_float4(sm[i * 4 + 0][t], sm[i * 4 + 1][t],
                               sm[i * 4 + 2][t], sm[i * 4 + 3][t]);
        *(float4*)(outp + i * 4) = v;
    }
}

// ---------------------------------------------------------------------------
// Kernel 2: weight -> A-fragment-ordered tf32 (verified layout)
// ---------------------------------------------------------------------------
__global__ void prep_w_kernel(const float* __restrict__ w) {
    int i = blockIdx.x * 256 + threadIdx.x;
    if (i >= KT * 8 * 32 * 4) return;
    int j    = i & 3;
    int lane = (i >> 2) & 31;
    int mt   = (i >> 7) & 7;
    int kt   = i >> 10;
    int g    = lane >> 2;
    int tid  = lane & 3;
    int co   = mt * 16 + g + ((j & 1) ? 8 : 0);
    int col  = tid + ((j >= 2) ? 4 : 0);
    int s    = kt >> 1;
    int c    = (kt & 1) * 8 + col;
    int dg   = s / KK;
    int k    = s - dg * KK;
    g_wa[i] = f2tf32(w[(co * CN + dg * CG + c) * KK + k]);
}

// ---------------------------------------------------------------------------
// Corner prefetch state (statically named, never dynamically indexed)
// ---------------------------------------------------------------------------
struct C4 { float4 c[4]; float w[4]; };

__device__ __forceinline__ void issue_c4(int s, int b, int ho, int p, int q,
                                         float dy, float dx, float m, C4& C) {
    int dg = s / KK, k = s - dg * KK;
    int ky = k / 3, kx = k - ky * 3;
    float sy = dy + (float)(ho - 1 + ky);   // STRIDE=1, PAD=1, DIL=1
    float sx = dx + (float)(p - 1 + kx);
    float y0f = floorf(sy), x0f = floorf(sx);
    float ly = sy - y0f, lx = sx - x0f;
    int y0 = (int)y0f, x0 = (int)x0f;
    float ww[4] = {(1.0f - ly) * (1.0f - lx) * m, (1.0f - ly) * lx * m,
                   ly * (1.0f - lx) * m,          ly * lx * m};
    const float* xb = g_xt + (b * DGN + dg) * (HN * WN * CG) + q * 4;
    #pragma unroll
    for (int i = 0; i < 4; i++) {
        int yy = y0 + (i >> 1), xx = x0 + (i & 1);
        bool v = (yy >= 0) & (yy < HN) & (xx >= 0) & (xx < WN);
        int cy = min(max(yy, 0), HN - 1), cx = min(max(xx, 0), WN - 1);
        C.c[i] = __ldg((const float4*)(xb + (cy * WN + cx) * CG));
        C.w[i] = v ? ww[i] : 0.0f;
    }
}

// ---------------------------------------------------------------------------
// Kernel 3: pair-sync depth-2 pipeline + tf32 mma.sync, 64-px blocks,
// 2 CTAs/SM. One __syncthreads per TWO stages (alternating buffer sets).
// Safety: set X written at pair i was last read by GEMM(pair i-2); every
// warp's passage through sync(i-1) proves GEMM(i-2) completion.
// ---------------------------------------------------------------------------
__global__ __launch_bounds__(256, 2)
void dcn_main_kernel(const float* __restrict__ offset,
                     const float* __restrict__ mask,
                     const float* __restrict__ bias,
                     float*       __restrict__ out) {
    int blk = blockIdx.x;                  // ((b*HO + ho)*2 + hr)
    int hr  = blk & 1;
    int ho  = (blk >> 1) & (HO - 1);
    int b   = blk >> 8;
    int t   = threadIdx.x;
    int wid = t >> 5;
    int lane = t & 31;

    // B frags: [set][stage-in-pair][kt][ntile(8)][lane][half] -> 16KB
    __shared__ __align__(16) uint32_t bfr[2][2][2][8][32][2];
    // A frags: [set][stage-in-pair][kt][mtile(8)][lane] uint4 -> 32KB
    __shared__ __align__(16) uint4 afrag[2][2][2][8][32];

    int m0 = (wid & 3) * 2;    // 2 mtiles per warp
    int n0 = (wid >> 2) * 4;   // 4 ntiles per warp

    // sampler mapping: 4 threads per pixel
    int q    = t & 3;
    int p    = t >> 2;         // local pixel (0..63)
    int pg   = hr * PXB + p;
    int kt   = q >> 1;
    int half = q & 1;

    float d[2][4][4];
    #pragma unroll
    for (int mi = 0; mi < 2; mi++)
        #pragma unroll
        for (int ni = 0; ni < 4; ni++)
            #pragma unroll
            for (int j = 0; j < 4; j++) d[mi][ni][j] = 0.0f;

    // ---- prologue ----
    C4 CE, CO;
    uint4 aPE0, aPE1, aPO0, aPO1;
    float dyE, dxE, mE, dyO, dxO, mO;
    const int OHW = HO * WO;
    const int obase = (b * (2 * NS)) * OHW + ho * WO + pg;
    const int mbase = (b * NS) * OHW + ho * WO + pg;
    {
        float dy = __ldg(offset + obase);
        float dx = __ldg(offset + obase + OHW);
        float mm = __ldg(mask + mbase);
        issue_c4(0, b, ho, pg, q, dy, dx, mm, CE);

        dy = __ldg(offset + obase + 2 * OHW);
        dx = __ldg(offset + obase + 3 * OHW);
        mm = __ldg(mask + mbase + OHW);
        issue_c4(1, b, ho, pg, q, dy, dx, mm, CO);

        dyE = __ldg(offset + obase + 4 * OHW);
        dxE = __ldg(offset + obase + 5 * OHW);
        mE  = __ldg(mask + mbase + 2 * OHW);
        dyO = __ldg(offset + obase + 6 * OHW);
        dxO = __ldg(offset + obase + 7 * OHW);
        mO  = __ldg(mask + mbase + 3 * OHW);

        aPE0 = __ldg((const uint4*)g_wa + t);
        aPE1 = __ldg((const uint4*)g_wa + t + 256);
        aPO0 = __ldg((const uint4*)(g_wa + 2048) + t);
        aPO1 = __ldg((const uint4*)(g_wa + 2048) + t + 256);
    }

    int nt = p >> 3;
    int lb = (p & 7) * 4;

    #pragma unroll 1
    for (int s = 0; s < NS; s += 2) {
        int set = (s >> 1) & 1;

        // ---- store prefetched A(s), A(s+1) ----
        {
            uint4* wdstE = (uint4*)&afrag[set][0][0][0][0];
            uint4* wdstO = (uint4*)&afrag[set][1][0][0][0];
            wdstE[t]       = aPE0;
            wdstE[t + 256] = aPE1;
            wdstO[t]       = aPO0;
            wdstO[t + 256] = aPO1;
        }

        // ---- combine corners(s) -> B frags (stage-in-pair 0) ----
        {
            float val[4];
            #pragma unroll
            for (int c = 0; c < 4; c++) {
                const float* f0 = (const float*)&CE.c[0];
                const float* f1 = (const float*)&CE.c[1];
                const float* f2 = (const float*)&CE.c[2];
                const float* f3 = (const float*)&CE.c[3];
                val[c] = CE.w[0] * f0[c] + CE.w[1] * f1[c]
                       + CE.w[2] * f2[c] + CE.w[3] * f3[c];
            }
            #pragma unroll
            for (int c = 0; c < 4; c++)
                bfr[set][0][kt][nt][lb + c][half] = f2tf32(val[c]);
        }
        // ---- combine corners(s+1) -> B frags (stage-in-pair 1) ----
        {
            float val[4];
            #pragma unroll
            for (int c = 0; c < 4; c++) {
                const float* f0 = (const float*)&CO.c[0];
                const float* f1 = (const float*)&CO.c[1];
                const float* f2 = (const float*)&CO.c[2];
                const float* f3 = (const float*)&CO.c[3];
                val[c] = CO.w[0] * f0[c] + CO.w[1] * f1[c]
                       + CO.w[2] * f2[c] + CO.w[3] * f3[c];
            }
            #pragma unroll
            for (int c = 0; c < 4; c++)
                bfr[set][1][kt][nt][lb + c][half] = f2tf32(val[c]);
        }

        // ---- issue corners(s+2)/(s+3); prefetch A(s+2)/(s+3); ofs deeper ----
        if (s + 2 < NS) {
            issue_c4(s + 2, b, ho, pg, q, dyE, dxE, mE, CE);
            issue_c4(s + 3, b, ho, pg, q, dyO, dxO, mO, CO);
            aPE0 = __ldg((const uint4*)(g_wa + (s + 2) * 2048) + t);
            aPE1 = __ldg((const uint4*)(g_wa + (s + 2) * 2048) + t + 256);
            aPO0 = __ldg((const uint4*)(g_wa + (s + 3) * 2048) + t);
            aPO1 = __ldg((const uint4*)(g_wa + (s + 3) * 2048) + t + 256);
            if (s + 4 < NS) {
                dyE = __ldg(offset + obase + (2 * (s + 4)) * OHW);
                dxE = __ldg(offset + obase + (2 * (s + 4) + 1) * OHW);
                mE  = __ldg(mask + mbase + (s + 4) * OHW);
                dyO = __ldg(offset + obase + (2 * (s + 5)) * OHW);
                dxO = __ldg(offset + obase + (2 * (s + 5) + 1) * OHW);
                mO  = __ldg(mask + mbase + (s + 5) * OHW);
            }
        }

        __syncthreads();   // frags(s, s+1) visible

        // ---- GEMM burst: 2 stages x 2 k8-slices x 2 mtiles x 4 ntiles ----
        #pragma unroll
        for (int st = 0; st < 2; st++) {
            #pragma unroll
            for (int k2 = 0; k2 < 2; k2++) {
                uint4 af[2];
                #pragma unroll
                for (int mi = 0; mi < 2; mi++)
                    af[mi] = afrag[set][st][k2][m0 + mi][lane];
                uint2 bf[4];
                #pragma unroll
                for (int ni = 0; ni < 4; ni++)
                    bf[ni] = *(const uint2*)&bfr[set][st][k2][n0 + ni][lane][0];
                #pragma unroll
                for (int mi = 0; mi < 2; mi++)
                    #pragma unroll
                    for (int ni = 0; ni < 4; ni++)
                        mma_tf32(d[mi][ni], (const uint32_t*)&af[mi],
                                 (const uint32_t*)&bf[ni]);
            }
        }
    }

    // ---- epilogue ----
    int g   = lane >> 2;
    int tid = lane & 3;
    #pragma unroll
    for (int mi = 0; mi < 2; mi++) {
        int co0 = (m0 + mi) * 16 + g;
        float bv0 = __ldg(bias + co0);
        float bv1 = __ldg(bias + co0 + 8);
        #pragma unroll
        for (int ni = 0; ni < 4; ni++) {
            int px = hr * PXB + (n0 + ni) * 8 + 2 * tid;
            float2 o0 = make_float2(d[mi][ni][0] + bv0, d[mi][ni][1] + bv0);
            float2 o1 = make_float2(d[mi][ni][2] + bv1, d[mi][ni][3] + bv1);
            *(float2*)(out + ((b * COUT + co0)     * HO + ho) * WO + px) = o0;
            *(float2*)(out + ((b * COUT + co0 + 8) * HO + ho) * WO + px) = o1;
        }
    }
}

// ---------------------------------------------------------------------------
// Launch
// ---------------------------------------------------------------------------
extern "C" void kernel_launch(void* const* d_in, const int* in_sizes, int n_in,
                              void* d_out, int out_size) {
    const float* x      = (const float*)d_in[0];
    const float* offset = (const float*)d_in[1];
    const float* mask   = (const float*)d_in[2];
    const float* weight = (const float*)d_in[3];
    const float* bias   = (const float*)d_in[4];
    float* out = (float*)d_out;

    transpose_x_kernel<<<BN * DGN * HN, 128>>>(x);
    prep_w_kernel<<<(KT * 8 * 32 * 4 + 255) / 256, 256>>>(weight);
    dcn_main_kernel<<<BN * HO * 2, 256>>>(offset, mask, bias, out);
}

// round 12
// speedup vs baseline: 2.8529x; 1.3206x over previous
#include <cuda_runtime.h>
#include <cuda_fp16.h>
#include <cstdint>

// Problem constants
#define BN   4
#define CN   128
#define HN   128
#define WN   128
#define COUT 128
#define DGN  8
#define CG   16
#define KK   9
#define HO   128
#define WO   128
#define NS   72         // (dg,k) positions == k16 slices (K = 1152)
#define PXB  64         // pixels per block

// Scratch
__device__ __align__(16) float g_xt[BN * DGN * HN * WN * CG];    // x -> (B,DG,H,W,Cg)
__device__ __align__(16) uint32_t g_wa[NS * 8 * 32 * 4];         // A-frag fp16x2 weights

__device__ __forceinline__ uint32_t pack_h2(float a, float b) {
    __half2 h = __floats2half2_rn(a, b);
    return *(uint32_t*)&h;
}
__device__ __forceinline__ void mma_f16(float* d, const uint32_t* a, const uint32_t* b) {
    asm volatile(
        "mma.sync.aligned.m16n8k16.row.col.f32.f16.f16.f32 "
        "{%0,%1,%2,%3}, {%4,%5,%6,%7}, {%8,%9}, {%0,%1,%2,%3};"
        : "+f"(d[0]), "+f"(d[1]), "+f"(d[2]), "+f"(d[3])
        : "r"(a[0]), "r"(a[1]), "r"(a[2]), "r"(a[3]), "r"(b[0]), "r"(b[1]));
}

// ---------------------------------------------------------------------------
// Kernel 1: transpose x (B,C,H,W) -> (B, DG, H, W, Cg)
// ---------------------------------------------------------------------------
__global__ void transpose_x_kernel(const float* __restrict__ x) {
    int blk = blockIdx.x;
    int y   = blk & (HN - 1);
    int bdg = blk >> 7;
    int b   = bdg >> 3;
    int dg  = bdg & 7;
    int t   = threadIdx.x;

    __shared__ float sm[CG][WN + 1];
    #pragma unroll
    for (int c = 0; c < CG; c++)
        sm[c][t] = x[((b * CN + dg * CG + c) * HN + y) * WN + t];
    __syncthreads();

    float* outp = g_xt + ((bdg * HN + y) * WN + t) * CG;
    #pragma unroll
    for (int i = 0; i < 4; i++) {
        float4 v = make_float4(sm[i * 4 + 0][t], sm[i * 4 + 1][t],
                               sm[i * 4 + 2][t], sm[i * 4 + 3][t]);
        *(float4*)(outp + i * 4) = v;
    }
}

// ---------------------------------------------------------------------------
// Kernel 2: weight -> A-fragment-ordered fp16x2 for m16n8k16.
// Stage s (16 channels), mtile mt, lane l (g=l>>2, tid=l&3), reg j:
//   co = mt*16 + g + (j&1)*8 ; kpair = tid*2 + (j>=2)*8 ; value half2(w[kp], w[kp+1])
// ---------------------------------------------------------------------------
__global__ void prep_w_kernel(const float* __restrict__ w) {
    int i = blockIdx.x * 256 + threadIdx.x;
    if (i >= NS * 8 * 32 * 4) return;
    int j    = i & 3;
    int lane = (i >> 2) & 31;
    int mt   = (i >> 7) & 7;
    int s    = i >> 10;
    int g    = lane >> 2;
    int tid  = lane & 3;
    int co   = mt * 16 + g + ((j & 1) ? 8 : 0);
    int kp   = tid * 2 + ((j >= 2) ? 8 : 0);
    int dg   = s / KK;
    int k    = s - dg * KK;
    float w0 = w[(co * CN + dg * CG + kp)     * KK + k];
    float w1 = w[(co * CN + dg * CG + kp + 1) * KK + k];
    g_wa[i] = pack_h2(w0, w1);
}

// ---------------------------------------------------------------------------
// Corner prefetch state (statically named, never dynamically indexed)
// ---------------------------------------------------------------------------
struct C4 { float4 c[4]; float w[4]; };

__device__ __forceinline__ void issue_c4(int s, int b, int ho, int p, int q,
                                         float dy, float dx, float m, C4& C) {
    int dg = s / KK, k = s - dg * KK;
    int ky = k / 3, kx = k - ky * 3;
    float sy = dy + (float)(ho - 1 + ky);   // STRIDE=1, PAD=1, DIL=1
    float sx = dx + (float)(p - 1 + kx);
    float y0f = floorf(sy), x0f = floorf(sx);
    float ly = sy - y0f, lx = sx - x0f;
    int y0 = (int)y0f, x0 = (int)x0f;
    float ww[4] = {(1.0f - ly) * (1.0f - lx) * m, (1.0f - ly) * lx * m,
                   ly * (1.0f - lx) * m,          ly * lx * m};
    const float* xb = g_xt + (b * DGN + dg) * (HN * WN * CG) + q * 4;
    #pragma unroll
    for (int i = 0; i < 4; i++) {
        int yy = y0 + (i >> 1), xx = x0 + (i & 1);
        bool v = (yy >= 0) & (yy < HN) & (xx >= 0) & (xx < WN);
        int cy = min(max(yy, 0), HN - 1), cx = min(max(xx, 0), WN - 1);
        C.c[i] = __ldg((const float4*)(xb + (cy * WN + cx) * CG));
        C.w[i] = v ? ww[i] : 0.0f;
    }
}

// ---------------------------------------------------------------------------
// Kernel 3: pair-sync depth-2 pipeline + fp16 m16n8k16 mma.sync.
// 64-px blocks, 2 CTAs/SM, 256 threads / 8 warps, warp tile 32(co) x 32(px).
// One __syncthreads per TWO stages; 16 MMAs per warp per pair.
// ---------------------------------------------------------------------------
__global__ __launch_bounds__(256, 2)
void dcn_main_kernel(const float* __restrict__ offset,
                     const float* __restrict__ mask,
                     const float* __restrict__ bias,
                     float*       __restrict__ out) {
    int blk = blockIdx.x;                  // ((b*HO + ho)*2 + hr)
    int hr  = blk & 1;
    int ho  = (blk >> 1) & (HO - 1);
    int b   = blk >> 8;
    int t   = threadIdx.x;
    int wid = t >> 5;
    int lane = t & 31;

    // B frags: [set][stage-in-pair][ntile(8)][lane][reg(2)] u32 -> 8KB
    __shared__ __align__(16) uint32_t bfr[2][2][8][32][2];
    // A frags: [set][stage-in-pair][mtile(8)][lane] uint4       -> 16KB
    __shared__ __align__(16) uint4 afrag[2][2][8][32];

    int m0 = (wid & 3) * 2;    // 2 mtiles per warp
    int n0 = (wid >> 2) * 4;   // 4 ntiles per warp

    // sampler mapping: 4 threads per pixel
    int q    = t & 3;          // channel quarter (c = q*4 .. q*4+3)
    int p    = t >> 2;         // local pixel (0..63)
    int pg   = hr * PXB + p;

    float d[2][4][4];
    #pragma unroll
    for (int mi = 0; mi < 2; mi++)
        #pragma unroll
        for (int ni = 0; ni < 4; ni++)
            #pragma unroll
            for (int j = 0; j < 4; j++) d[mi][ni][j] = 0.0f;

    // ---- prologue ----
    C4 CE, CO;
    uint4 aPE, aPO;
    float dyE, dxE, mE, dyO, dxO, mO;
    const int OHW = HO * WO;
    const int obase = (b * (2 * NS)) * OHW + ho * WO + pg;
    const int mbase = (b * NS) * OHW + ho * WO + pg;
    {
        float dy = __ldg(offset + obase);
        float dx = __ldg(offset + obase + OHW);
        float mm = __ldg(mask + mbase);
        issue_c4(0, b, ho, pg, q, dy, dx, mm, CE);

        dy = __ldg(offset + obase + 2 * OHW);
        dx = __ldg(offset + obase + 3 * OHW);
        mm = __ldg(mask + mbase + OHW);
        issue_c4(1, b, ho, pg, q, dy, dx, mm, CO);

        dyE = __ldg(offset + obase + 4 * OHW);
        dxE = __ldg(offset + obase + 5 * OHW);
        mE  = __ldg(mask + mbase + 2 * OHW);
        dyO = __ldg(offset + obase + 6 * OHW);
        dxO = __ldg(offset + obase + 7 * OHW);
        mO  = __ldg(mask + mbase + 3 * OHW);

        aPE = __ldg((const uint4*)g_wa + t);
        aPO = __ldg((const uint4*)(g_wa + 1024) + t);
    }

    int nt    = p >> 3;
    int lb    = (p & 7) * 4 + (q & 1) * 2;   // B-frag lane base for this thread
    int breg  = q >> 1;                      // b0 vs b1

    #pragma unroll 1
    for (int s = 0; s < NS; s += 2) {
        int set = (s >> 1) & 1;

        // ---- store prefetched A(s), A(s+1) ----
        {
            ((uint4*)&afrag[set][0][0][0])[t] = aPE;
            ((uint4*)&afrag[set][1][0][0])[t] = aPO;
        }

        // ---- combine corners(s) -> B frags ----
        {
            float val[4];
            #pragma unroll
            for (int c = 0; c < 4; c++) {
                const float* f0 = (const float*)&CE.c[0];
                const float* f1 = (const float*)&CE.c[1];
                const float* f2 = (const float*)&CE.c[2];
                const float* f3 = (const float*)&CE.c[3];
                val[c] = CE.w[0] * f0[c] + CE.w[1] * f1[c]
                       + CE.w[2] * f2[c] + CE.w[3] * f3[c];
            }
            bfr[set][0][nt][lb][breg]     = pack_h2(val[0], val[1]);
            bfr[set][0][nt][lb + 1][breg] = pack_h2(val[2], val[3]);
        }
        // ---- combine corners(s+1) -> B frags ----
        {
            float val[4];
            #pragma unroll
            for (int c = 0; c < 4; c++) {
                const float* f0 = (const float*)&CO.c[0];
                const float* f1 = (const float*)&CO.c[1];
                const float* f2 = (const float*)&CO.c[2];
                const float* f3 = (const float*)&CO.c[3];
                val[c] = CO.w[0] * f0[c] + CO.w[1] * f1[c]
                       + CO.w[2] * f2[c] + CO.w[3] * f3[c];
            }
            bfr[set][1][nt][lb][breg]     = pack_h2(val[0], val[1]);
            bfr[set][1][nt][lb + 1][breg] = pack_h2(val[2], val[3]);
        }

        // ---- issue corners(s+2)/(s+3); prefetch A(s+2)/(s+3); ofs depth 4 ----
        if (s + 2 < NS) {
            issue_c4(s + 2, b, ho, pg, q, dyE, dxE, mE, CE);
            issue_c4(s + 3, b, ho, pg, q, dyO, dxO, mO, CO);
            aPE = __ldg((const uint4*)(g_wa + (s + 2) * 1024) + t);
            aPO = __ldg((const uint4*)(g_wa + (s + 3) * 1024) + t);
            if (s + 4 < NS) {
                dyE = __ldg(offset + obase + (2 * (s + 4)) * OHW);
                dxE = __ldg(offset + obase + (2 * (s + 4) + 1) * OHW);
                mE  = __ldg(mask + mbase + (s + 4) * OHW);
                dyO = __ldg(offset + obase + (2 * (s + 5)) * OHW);
                dxO = __ldg(offset + obase + (2 * (s + 5) + 1) * OHW);
                mO  = __ldg(mask + mbase + (s + 5) * OHW);
            }
        }

        __syncthreads();   // frags(s, s+1) visible

        // ---- GEMM burst: 2 stages x 2 mtiles x 4 ntiles m16n8k16 ----
        #pragma unroll
        for (int st = 0; st < 2; st++) {
            uint4 af[2];
            #pragma unroll
            for (int mi = 0; mi < 2; mi++)
                af[mi] = afrag[set][st][m0 + mi][lane];
            uint2 bf[4];
            #pragma unroll
            for (int ni = 0; ni < 4; ni++)
                bf[ni] = *(const uint2*)&bfr[set][st][n0 + ni][lane][0];
            #pragma unroll
            for (int mi = 0; mi < 2; mi++)
                #pragma unroll
                for (int ni = 0; ni < 4; ni++)
                    mma_f16(d[mi][ni], (const uint32_t*)&af[mi],
                            (const uint32_t*)&bf[ni]);
        }
    }

    // ---- epilogue ----
    int g   = lane >> 2;
    int tid = lane & 3;
    #pragma unroll
    for (int mi = 0; mi < 2; mi++) {
        int co0 = (m0 + mi) * 16 + g;
        float bv0 = __ldg(bias + co0);
        float bv1 = __ldg(bias + co0 + 8);
        #pragma unroll
        for (int ni = 0; ni < 4; ni++) {
            int px = hr * PXB + (n0 + ni) * 8 + 2 * tid;
            float2 o0 = make_float2(d[mi][ni][0] + bv0, d[mi][ni][1] + bv0);
            float2 o1 = make_float2(d[mi][ni][2] + bv1, d[mi][ni][3] + bv1);
            *(float2*)(out + ((b * COUT + co0)     * HO + ho) * WO + px) = o0;
            *(float2*)(out + ((b * COUT + co0 + 8) * HO + ho) * WO + px) = o1;
        }
    }
}

// ---------------------------------------------------------------------------
// Launch
// ---------------------------------------------------------------------------
extern "C" void kernel_launch(void* const* d_in, const int* in_sizes, int n_in,
                              void* d_out, int out_size) {
    const float* x      = (const float*)d_in[0];
    const float* offset = (const float*)d_in[1];
    const float* mask   = (const float*)d_in[2];
    const float* weight = (const float*)d_in[3];
    const float* bias   = (const float*)d_in[4];
    float* out = (float*)d_out;

    transpose_x_kernel<<<BN * DGN * HN, 128>>>(x);
    prep_w_kernel<<<(NS * 8 * 32 * 4 + 255) / 256, 256>>>(weight);
    dcn_main_kernel<<<BN * HO * 2, 256>>>(offset, mask, bias, out);
}

// round 13
// speedup vs baseline: 3.0534x; 1.0703x over previous
#include <cuda_runtime.h>
#include <cuda_fp16.h>
#include <cstdint>

// Problem constants
#define BN   4
#define CN   128
#define HN   128
#define WN   128
#define COUT 128
#define DGN  8
#define CG   16
#define KK   9
#define HO   128
#define WO   128
#define NS   72         // (dg,k) positions == k16 slices (K = 1152)
#define PXB  64         // pixels per block

// Scratch
__device__ __align__(16) __half g_xt[BN * DGN * HN * WN * CG];   // x -> (B,DG,H,W,Cg) fp16
__device__ __align__(16) uint32_t g_wa[NS * 8 * 32 * 4];         // A-frag fp16x2 weights

__device__ __forceinline__ uint32_t pack_h2(float a, float b) {
    __half2 h = __floats2half2_rn(a, b);
    return *(uint32_t*)&h;
}
__device__ __forceinline__ void mma_f16(float* d, const uint32_t* a, const uint32_t* b) {
    asm volatile(
        "mma.sync.aligned.m16n8k16.row.col.f32.f16.f16.f32 "
        "{%0,%1,%2,%3}, {%4,%5,%6,%7}, {%8,%9}, {%0,%1,%2,%3};"
        : "+f"(d[0]), "+f"(d[1]), "+f"(d[2]), "+f"(d[3])
        : "r"(a[0]), "r"(a[1]), "r"(a[2]), "r"(a[3]), "r"(b[0]), "r"(b[1]));
}

// ---------------------------------------------------------------------------
// Kernel 1: transpose x (B,C,H,W) -> (B, DG, H, W, Cg) in fp16
// ---------------------------------------------------------------------------
__global__ void transpose_x_kernel(const float* __restrict__ x) {
    int blk = blockIdx.x;
    int y   = blk & (HN - 1);
    int bdg = blk >> 7;
    int b   = bdg >> 3;
    int dg  = bdg & 7;
    int t   = threadIdx.x;

    __shared__ float sm[CG][WN + 1];
    #pragma unroll
    for (int c = 0; c < CG; c++)
        sm[c][t] = x[((b * CN + dg * CG + c) * HN + y) * WN + t];
    __syncthreads();

    __half* outp = g_xt + ((bdg * HN + y) * WN + t) * CG;
    #pragma unroll
    for (int i = 0; i < 2; i++) {
        uint4 u;
        u.x = pack_h2(sm[i * 8 + 0][t], sm[i * 8 + 1][t]);
        u.y = pack_h2(sm[i * 8 + 2][t], sm[i * 8 + 3][t]);
        u.z = pack_h2(sm[i * 8 + 4][t], sm[i * 8 + 5][t]);
        u.w = pack_h2(sm[i * 8 + 6][t], sm[i * 8 + 7][t]);
        *(uint4*)(outp + i * 8) = u;
    }
}

// ---------------------------------------------------------------------------
// Kernel 2: weight -> A-fragment-ordered fp16x2 for m16n8k16 (verified)
// ---------------------------------------------------------------------------
__global__ void prep_w_kernel(const float* __restrict__ w) {
    int i = blockIdx.x * 256 + threadIdx.x;
    if (i >= NS * 8 * 32 * 4) return;
    int j    = i & 3;
    int lane = (i >> 2) & 31;
    int mt   = (i >> 7) & 7;
    int s    = i >> 10;
    int g    = lane >> 2;
    int tid  = lane & 3;
    int co   = mt * 16 + g + ((j & 1) ? 8 : 0);
    int kp   = tid * 2 + ((j >= 2) ? 8 : 0);
    int dg   = s / KK;
    int k    = s - dg * KK;
    float w0 = w[(co * CN + dg * CG + kp)     * KK + k];
    float w1 = w[(co * CN + dg * CG + kp + 1) * KK + k];
    g_wa[i] = pack_h2(w0, w1);
}

// ---------------------------------------------------------------------------
// Corner prefetch state: 4 corners x 4 fp16 channels (uint2 each) + weights
// ---------------------------------------------------------------------------
struct C4 { uint2 c[4]; float w[4]; };

__device__ __forceinline__ void issue_c4(int s, int b, int ho, int p, int q,
                                         float dy, float dx, float m, C4& C) {
    int dg = s / KK, k = s - dg * KK;
    int ky = k / 3, kx = k - ky * 3;
    float sy = dy + (float)(ho - 1 + ky);   // STRIDE=1, PAD=1, DIL=1
    float sx = dx + (float)(p - 1 + kx);
    float y0f = floorf(sy), x0f = floorf(sx);
    float ly = sy - y0f, lx = sx - x0f;
    int y0 = (int)y0f, x0 = (int)x0f;
    float ww[4] = {(1.0f - ly) * (1.0f - lx) * m, (1.0f - ly) * lx * m,
                   ly * (1.0f - lx) * m,          ly * lx * m};
    const __half* xb = g_xt + (b * DGN + dg) * (HN * WN * CG) + q * 4;
    #pragma unroll
    for (int i = 0; i < 4; i++) {
        int yy = y0 + (i >> 1), xx = x0 + (i & 1);
        bool v = (yy >= 0) & (yy < HN) & (xx >= 0) & (xx < WN);
        int cy = min(max(yy, 0), HN - 1), cx = min(max(xx, 0), WN - 1);
        C.c[i] = __ldg((const uint2*)(xb + (cy * WN + cx) * CG));
        C.w[i] = v ? ww[i] : 0.0f;
    }
}

__device__ __forceinline__ void combine_c4(const C4& C, float* val) {
    val[0] = val[1] = val[2] = val[3] = 0.0f;
    #pragma unroll
    for (int i = 0; i < 4; i++) {
        const __half2* h = (const __half2*)&C.c[i];
        float2 a = __half22float2(h[0]);
        float2 b = __half22float2(h[1]);
        val[0] += C.w[i] * a.x;  val[1] += C.w[i] * a.y;
        val[2] += C.w[i] * b.x;  val[3] += C.w[i] * b.y;
    }
}

// ---------------------------------------------------------------------------
// Kernel 3: pair-sync depth-2 pipeline + fp16 m16n8k16 mma.sync.
// 64-px blocks, 2 CTAs/SM, 256 threads / 8 warps, warp tile 32(co) x 32(px).
// fp16 x_t gathers: half the L1tex wavefronts and L2 traffic of fp32.
// ---------------------------------------------------------------------------
__global__ __launch_bounds__(256, 2)
void dcn_main_kernel(const float* __restrict__ offset,
                     const float* __restrict__ mask,
                     const float* __restrict__ bias,
                     float*       __restrict__ out) {
    int blk = blockIdx.x;                  // ((b*HO + ho)*2 + hr)
    int hr  = blk & 1;
    int ho  = (blk >> 1) & (HO - 1);
    int b   = blk >> 8;
    int t   = threadIdx.x;
    int wid = t >> 5;
    int lane = t & 31;

    // B frags: [set][stage-in-pair][ntile(8)][lane][reg(2)] u32 -> 8KB
    __shared__ __align__(16) uint32_t bfr[2][2][8][32][2];
    // A frags: [set][stage-in-pair][mtile(8)][lane] uint4       -> 16KB
    __shared__ __align__(16) uint4 afrag[2][2][8][32];

    int m0 = (wid & 3) * 2;    // 2 mtiles per warp
    int n0 = (wid >> 2) * 4;   // 4 ntiles per warp

    // sampler mapping: 4 threads per pixel
    int q    = t & 3;          // channel quarter (c = q*4 .. q*4+3)
    int p    = t >> 2;         // local pixel (0..63)
    int pg   = hr * PXB + p;

    float d[2][4][4];
    #pragma unroll
    for (int mi = 0; mi < 2; mi++)
        #pragma unroll
        for (int ni = 0; ni < 4; ni++)
            #pragma unroll
            for (int j = 0; j < 4; j++) d[mi][ni][j] = 0.0f;

    // ---- prologue ----
    C4 CE, CO;
    uint4 aPE, aPO;
    float dyE, dxE, mE, dyO, dxO, mO;
    const int OHW = HO * WO;
    const int obase = (b * (2 * NS)) * OHW + ho * WO + pg;
    const int mbase = (b * NS) * OHW + ho * WO + pg;
    {
        float dy = __ldg(offset + obase);
        float dx = __ldg(offset + obase + OHW);
        float mm = __ldg(mask + mbase);
        issue_c4(0, b, ho, pg, q, dy, dx, mm, CE);

        dy = __ldg(offset + obase + 2 * OHW);
        dx = __ldg(offset + obase + 3 * OHW);
        mm = __ldg(mask + mbase + OHW);
        issue_c4(1, b, ho, pg, q, dy, dx, mm, CO);

        dyE = __ldg(offset + obase + 4 * OHW);
        dxE = __ldg(offset + obase + 5 * OHW);
        mE  = __ldg(mask + mbase + 2 * OHW);
        dyO = __ldg(offset + obase + 6 * OHW);
        dxO = __ldg(offset + obase + 7 * OHW);
        mO  = __ldg(mask + mbase + 3 * OHW);

        aPE = __ldg((const uint4*)g_wa + t);
        aPO = __ldg((const uint4*)(g_wa + 1024) + t);
    }

    int nt    = p >> 3;
    int lb    = (p & 7) * 4 + (q & 1) * 2;   // B-frag lane base
    int breg  = q >> 1;                      // b0 vs b1

    #pragma unroll 1
    for (int s = 0; s < NS; s += 2) {
        int set = (s >> 1) & 1;

        // ---- store prefetched A(s), A(s+1) ----
        ((uint4*)&afrag[set][0][0][0])[t] = aPE;
        ((uint4*)&afrag[set][1][0][0])[t] = aPO;

        // ---- combine corners(s), (s+1) -> B frags ----
        {
            float val[4];
            combine_c4(CE, val);
            bfr[set][0][nt][lb][breg]     = pack_h2(val[0], val[1]);
            bfr[set][0][nt][lb + 1][breg] = pack_h2(val[2], val[3]);
            combine_c4(CO, val);
            bfr[set][1][nt][lb][breg]     = pack_h2(val[0], val[1]);
            bfr[set][1][nt][lb + 1][breg] = pack_h2(val[2], val[3]);
        }

        // ---- issue corners(s+2)/(s+3); prefetch A(s+2)/(s+3); ofs depth 4 ----
        if (s + 2 < NS) {
            issue_c4(s + 2, b, ho, pg, q, dyE, dxE, mE, CE);
            issue_c4(s + 3, b, ho, pg, q, dyO, dxO, mO, CO);
            aPE = __ldg((const uint4*)(g_wa + (s + 2) * 1024) + t);
            aPO = __ldg((const uint4*)(g_wa + (s + 3) * 1024) + t);
            if (s + 4 < NS) {
                dyE = __ldg(offset + obase + (2 * (s + 4)) * OHW);
                dxE = __ldg(offset + obase + (2 * (s + 4) + 1) * OHW);
                mE  = __ldg(mask + mbase + (s + 4) * OHW);
                dyO = __ldg(offset + obase + (2 * (s + 5)) * OHW);
                dxO = __ldg(offset + obase + (2 * (s + 5) + 1) * OHW);
                mO  = __ldg(mask + mbase + (s + 5) * OHW);
            }
        }

        __syncthreads();   // frags(s, s+1) visible

        // ---- GEMM burst: 2 stages x 2 mtiles x 4 ntiles m16n8k16 ----
        #pragma unroll
        for (int st = 0; st < 2; st++) {
            uint4 af[2];
            #pragma unroll
            for (int mi = 0; mi < 2; mi++)
                af[mi] = afrag[set][st][m0 + mi][lane];
            uint2 bf[4];
            #pragma unroll
            for (int ni = 0; ni < 4; ni++)
                bf[ni] = *(const uint2*)&bfr[set][st][n0 + ni][lane][0];
            #pragma unroll
            for (int mi = 0; mi < 2; mi++)
                #pragma unroll
                for (int ni = 0; ni < 4; ni++)
                    mma_f16(d[mi][ni], (const uint32_t*)&af[mi],
                            (const uint32_t*)&bf[ni]);
        }
    }

    // ---- epilogue ----
    int g   = lane >> 2;
    int tid = lane & 3;
    #pragma unroll
    for (int mi = 0; mi < 2; mi++) {
        int co0 = (m0 + mi) * 16 + g;
        float bv0 = __ldg(bias + co0);
        float bv1 = __ldg(bias + co0 + 8);
        #pragma unroll
        for (int ni = 0; ni < 4; ni++) {
            int px = hr * PXB + (n0 + ni) * 8 + 2 * tid;
            float2 o0 = make_float2(d[mi][ni][0] + bv0, d[mi][ni][1] + bv0);
            float2 o1 = make_float2(d[mi][ni][2] + bv1, d[mi][ni][3] + bv1);
            *(float2*)(out + ((b * COUT + co0)     * HO + ho) * WO + px) = o0;
            *(float2*)(out + ((b * COUT + co0 + 8) * HO + ho) * WO + px) = o1;
        }
    }
}

// ---------------------------------------------------------------------------
// Launch
// ---------------------------------------------------------------------------
extern "C" void kernel_launch(void* const* d_in, const int* in_sizes, int n_in,
                              void* d_out, int out_size) {
    const float* x      = (const float*)d_in[0];
    const float* offset = (const float*)d_in[1];
    const float* mask   = (const float*)d_in[2];
    const float* weight = (const float*)d_in[3];
    const float* bias   = (const float*)d_in[4];
    float* out = (float*)d_out;

    transpose_x_kernel<<<BN * DGN * HN, 128>>>(x);
    prep_w_kernel<<<(NS * 8 * 32 * 4 + 255) / 256, 256>>>(weight);
    dcn_main_kernel<<<BN * HO * 2, 256>>>(offset, mask, bias, out);
}